// round 14
// baseline (speedup 1.0000x reference)
#include <cuda_runtime.h>
#include <cuda_fp16.h>
#include <math.h>
#include <stdint.h>

#define B_ 64
#define S_ 512
#define DIN 1024
#define HID 4096
#define HS 1024
#define NCTA 128
#define RTHREADS 1024

// ---------------------------------------------------------------------------
// helpers
// ---------------------------------------------------------------------------
__device__ __forceinline__ uint32_t smem_to_u32(const void* p) {
    uint32_t a;
    asm("{ .reg .u64 t; cvta.to.shared.u64 t, %1; cvt.u32.u64 %0, t; }"
        : "=r"(a) : "l"(p));
    return a;
}

#define LDSM4(r0, r1, r2, r3, addr)                                        \
    asm volatile("ldmatrix.sync.aligned.m8n8.x4.shared.b16 {%0,%1,%2,%3}, [%4];" \
                 : "=r"(r0), "=r"(r1), "=r"(r2), "=r"(r3) : "r"(addr))

#define MMA16816(c, a0, a1, a2, a3, b0, b1)                                \
    asm volatile("mma.sync.aligned.m16n8k16.row.col.f32.f16.f16.f32 "      \
                 "{%0,%1,%2,%3}, {%4,%5,%6,%7}, {%8,%9}, {%0,%1,%2,%3};"   \
                 : "+f"((c)[0]), "+f"((c)[1]), "+f"((c)[2]), "+f"((c)[3])  \
                 : "r"(a0), "r"(a1), "r"(a2), "r"(a3), "r"(b0), "r"(b1))

#define CP16(d, s) \
    asm volatile("cp.async.cg.shared.global [%0], [%1], 16;" :: "r"(d), "l"(s))
#define CPCOMMIT() asm volatile("cp.async.commit_group;" ::: "memory")
#define CPWAIT(n) asm volatile("cp.async.wait_group %0;" :: "n"(n) : "memory")

// ---------------------------------------------------------------------------
// Globals (static scratch)
// ---------------------------------------------------------------------------
__device__ float g_xg[(size_t)S_ * B_ * HID];     // [s][b][4096]
__device__ __half g_xh[(size_t)B_ * S_ * DIN];    // x as fp16
__device__ __half g_wxh[(size_t)HID * DIN];       // wx (single-term fp16)
__device__ __half g_hh[2][B_ * HS];               // double-buffered hidden (fp16)
__device__ unsigned g_bar;

__global__ void init_state() {
    int t = blockIdx.x * blockDim.x + threadIdx.x;
    if (t == 0) g_bar = 0u;
    if (t < B_ * HS / 2) ((uint32_t*)g_hh[0])[t] = 0u;
}

// ---------------------------------------------------------------------------
// Convert x -> fp16, wx -> fp16 (single term)
// ---------------------------------------------------------------------------
__global__ void convert_inputs(const float* __restrict__ x,
                               const float* __restrict__ wx) {
    int t = blockIdx.x * blockDim.x + threadIdx.x;
    int stride = gridDim.x * blockDim.x;
    for (int i = t; i < HID * DIN / 4; i += stride) {
        float4 w = ((const float4*)wx)[i];
        ((__half2*)g_wxh)[i * 2 + 0] =
            __half2(__float2half_rn(w.x), __float2half_rn(w.y));
        ((__half2*)g_wxh)[i * 2 + 1] =
            __half2(__float2half_rn(w.z), __float2half_rn(w.w));
    }
    for (int i = t; i < B_ * S_ * DIN / 4; i += stride) {
        float4 v = ((const float4*)x)[i];
        ((__half2*)g_xh)[i * 2 + 0] = __half2(__float2half_rn(v.x), __float2half_rn(v.y));
        ((__half2*)g_xh)[i * 2 + 1] = __half2(__float2half_rn(v.z), __float2half_rn(v.w));
    }
}

// ---------------------------------------------------------------------------
// xg GEMM via mma.sync (single-term fp16) — occupancy 2 CTAs/SM
// ---------------------------------------------------------------------------
#define XG_SA 0
#define XG_SB 32768
#define XG_SMEM 65536

__global__ void __launch_bounds__(256, 2)
xg_gemm_mma(const float* __restrict__ bx, const float* __restrict__ bh) {
    extern __shared__ char smem[];
    uint32_t sb = smem_to_u32(smem);
    const int tid = threadIdx.x;
    const int wid = tid >> 5;
    const int lane = tid & 31;
    const int m0 = blockIdx.x * 128;
    const int n0 = blockIdx.y * 128;
    const int wm = (wid >> 2) * 64;
    const int wn = (wid & 3) * 32;

    const int sr = tid >> 1;
    const int sq0 = (tid & 1) * 4;
    const uint32_t s_sw = (uint32_t)((sr & 7) << 4);
    const int am = m0 + sr;
    const __half* asrc = g_xh + ((size_t)((am & 63) * S_ + (am >> 6))) * DIN;
    const __half* bsrc = g_wxh + (size_t)(n0 + sr) * DIN;

    const uint32_t a_k2 = (uint32_t)((lane >> 4) << 4);
    uint32_t a_base[4], a_swz[4];
#pragma unroll
    for (int mi = 0; mi < 4; mi++) {
        int ar = wm + mi * 16 + (lane & 15);
        a_base[mi] = (uint32_t)ar * 128;
        a_swz[mi] = (uint32_t)((ar & 7) << 4);
    }
    const uint32_t b_k2 = (uint32_t)(((lane >> 3) & 1) << 4);
    uint32_t b_base[2], b_swz[2];
#pragma unroll
    for (int ni = 0; ni < 2; ni++) {
        int bc = wn + ni * 16 + (lane & 7) + ((lane >> 4) << 3);
        b_base[ni] = (uint32_t)bc * 128;
        b_swz[ni] = (uint32_t)((bc & 7) << 4);
    }

    float acc[4][4][4];
#pragma unroll
    for (int i = 0; i < 4; i++)
#pragma unroll
        for (int j = 0; j < 4; j++)
#pragma unroll
            for (int q = 0; q < 4; q++) acc[i][j][q] = 0.0f;

    {
        uint32_t da = sb + XG_SA + (uint32_t)sr * 128;
        uint32_t db = sb + XG_SB + (uint32_t)sr * 128;
#pragma unroll
        for (int j = 0; j < 4; j++) {
            int q = sq0 + j;
            uint32_t sw = ((uint32_t)(q * 16)) ^ s_sw;
            CP16(da + sw, asrc + q * 8);
            CP16(db + sw, bsrc + q * 8);
        }
        CPCOMMIT();
    }

#pragma unroll 1
    for (int ch = 0; ch < 16; ch++) {
        const uint32_t buf = (uint32_t)(ch & 1);
        if (ch < 15) {
            const int kb = (ch + 1) * 64;
            uint32_t da = sb + XG_SA + (buf ^ 1u) * 16384u + (uint32_t)sr * 128;
            uint32_t db = sb + XG_SB + (buf ^ 1u) * 16384u + (uint32_t)sr * 128;
#pragma unroll
            for (int j = 0; j < 4; j++) {
                int q = sq0 + j;
                uint32_t sw = ((uint32_t)(q * 16)) ^ s_sw;
                CP16(da + sw, asrc + kb + q * 8);
                CP16(db + sw, bsrc + kb + q * 8);
            }
            CPCOMMIT();
            CPWAIT(1);
        } else {
            CPWAIT(0);
        }
        __syncthreads();

        const uint32_t abase = sb + XG_SA + buf * 16384u;
        const uint32_t bbase = sb + XG_SB + buf * 16384u;
#pragma unroll
        for (int k16 = 0; k16 < 4; k16++) {
            const uint32_t ka = (uint32_t)(k16 * 32);
            uint32_t a[4][4];
#pragma unroll
            for (int mi = 0; mi < 4; mi++)
                LDSM4(a[mi][0], a[mi][1], a[mi][2], a[mi][3],
                      abase + a_base[mi] + ((ka + a_k2) ^ a_swz[mi]));
            uint32_t bf[2][4];
#pragma unroll
            for (int ni = 0; ni < 2; ni++) {
                uint32_t bo = b_base[ni] + ((ka + b_k2) ^ b_swz[ni]);
                LDSM4(bf[ni][0], bf[ni][1], bf[ni][2], bf[ni][3], bbase + bo);
            }
#pragma unroll
            for (int mi = 0; mi < 4; mi++)
#pragma unroll
                for (int ni = 0; ni < 2; ni++) {
                    MMA16816(acc[mi][ni * 2 + 0], a[mi][0], a[mi][1], a[mi][2],
                             a[mi][3], bf[ni][0], bf[ni][1]);
                    MMA16816(acc[mi][ni * 2 + 1], a[mi][0], a[mi][1], a[mi][2],
                             a[mi][3], bf[ni][2], bf[ni][3]);
                }
        }
        __syncthreads();
    }

    const int tr = lane >> 2;
    const int tc = (lane & 3) * 2;
#pragma unroll
    for (int ni = 0; ni < 4; ni++) {
        int n = n0 + wn + ni * 8 + tc;
        float b0 = bx[n] + bh[n];
        float b1 = bx[n + 1] + bh[n + 1];
#pragma unroll
        for (int mi = 0; mi < 4; mi++) {
            int mrow = m0 + wm + mi * 16 + tr;
            float* d0 = g_xg + (size_t)mrow * HID + n;
            float* d1 = g_xg + (size_t)(mrow + 8) * HID + n;
            *(float2*)d0 = make_float2(acc[mi][ni][0] + b0, acc[mi][ni][1] + b1);
            *(float2*)d1 = make_float2(acc[mi][ni][2] + b0, acc[mi][ni][3] + b1);
        }
    }
}

// ---------------------------------------------------------------------------
// Persistent recurrence: 1024 threads, k-split-4 x 4m x 2n warp layout
// ---------------------------------------------------------------------------
__device__ __forceinline__ float sigf(float x) { return 1.0f / (1.0f + __expf(-x)); }
__device__ __forceinline__ float tanhfast(float x) {
    float ax = fabsf(x);
    float e = __expf(-2.0f * ax);
    float r = (1.0f - e) / (1.0f + e);
    return copysignf(r, x);
}

__device__ __forceinline__ void grid_barrier(unsigned target) {
    __syncthreads();
    if (threadIdx.x == 0) {
        asm volatile("red.release.gpu.global.add.u32 [%0], %1;"
                     :: "l"(&g_bar), "r"(1u) : "memory");
        unsigned v;
        do {
            asm volatile("ld.acquire.gpu.global.u32 %0, [%1];"
                         : "=r"(v) : "l"(&g_bar));
        } while ((int)(v - target) < 0);
    }
    __syncthreads();
}

// smem layout (bytes)
#define SM_WH 0              /* 32 cols x 2048 B = 65536 */
#define SM_HST 65536         /* 4 ring bufs x 16KB = 65536 */
#define SM_GATES 131072      /* 4 k-slices x 64 x 34 f32 = 34816 */
#define SMEM_TOTAL (SM_GATES + 4 * 64 * 34 * 4)

__global__ void __launch_bounds__(RTHREADS, 1)
lstm_persist(const float* __restrict__ wh, float* __restrict__ out, int do_tail) {
    extern __shared__ char smem[];
    uint32_t sb = smem_to_u32(smem);
    float* gates = (float*)(smem + SM_GATES);

    const int tid = threadIdx.x;
    const int wid = tid >> 5;
    const int lane = tid & 31;
    const int j0 = blockIdx.x * 8;

    // --- one-time: this CTA's 32 wh rows as fp16 into smem [col][k] ---
    {
        const int c = tid >> 5;                      // col 0..31
        const int kb = (tid & 31) * 32;              // k base (32 k per thread)
        const int n = (c >> 3) * HS + j0 + (c & 7);
        const float* wr = wh + (size_t)n * HS;
        const uint32_t swz = (uint32_t)((c & 7) << 4);
#pragma unroll 4
        for (int i = 0; i < 8; i++) {
            int k = kb + i * 4;
            float4 w4 = *(const float4*)(wr + k);
            __half h0 = __float2half_rn(w4.x);
            __half h1 = __float2half_rn(w4.y);
            __half h2 = __float2half_rn(w4.z);
            __half h3 = __float2half_rn(w4.w);
            uint32_t off = (uint32_t)(c * 2048) + (((uint32_t)(k * 2)) ^ swz);
            *(__half2*)(smem + SM_WH + off) = __half2(h0, h1);
            *(__half2*)(smem + SM_WH + off + 4) = __half2(h2, h3);
        }
    }
    __syncthreads();

    // warp decomposition: ks = k-slice quarter, wm/wn as before
    const int ks = wid >> 3;                 // 0..3
    const int wsub = wid & 7;
    const int wm = (wsub >> 1) << 4;
    const int wn = (wsub & 1) << 4;

    // A ldmatrix (16x16 tile, 256B rows in 16KB ring buf, swizzled)
    const int ar = wm + (lane & 15);
    const uint32_t a_row = (uint32_t)ar * 256;
    const uint32_t a_k2 = (uint32_t)((lane >> 4) << 4);
    const uint32_t a_swz = (uint32_t)((ar & 7) << 4);

    // B ldmatrix (cols as rows, 2048B col stride, swizzled)
    const int bc = wn + (lane & 7) + ((lane >> 4) << 3);
    const uint32_t b_row = (uint32_t)bc * 2048;
    const uint32_t b_k2 = (uint32_t)(((lane >> 3) & 1) << 4);
    const uint32_t b_swz = (uint32_t)((bc & 7) << 4);

    // this warp's k offset within a chunk (bytes): quarter = 2 k16 = 64 B
    const uint32_t kslice2 = (uint32_t)(ks * 64);

    // cp.async staging: 1024 threads, row = tid>>4, 8 k elems (16B) each
    const int srow = tid >> 4;
    const int skq = (tid & 15) * 8;
    const uint32_t s_swz = (uint32_t)((srow & 7) << 4);

    // distributed update: first 512 threads, 1 (batch, unit) pair each
    const int ub = (tid & 511) >> 3;         // batch 0..63
    const int uj = tid & 7;                  // unit 0..7
    const bool updater = tid < 512;

    float creg = 0.0f;

    for (int s = 0; s < S_; s++) {
        const int p = s & 1;
        const __half* hsrc = g_hh[p];

        // stage chunks 0,1,2 first (start L2 fetch ASAP)
#pragma unroll
        for (int c0 = 0; c0 < 3; c0++) {
            const __half* src = hsrc + srow * HS + c0 * 128 + skq;
            uint32_t dbase = sb + SM_HST + (uint32_t)c0 * 16384u +
                             (uint32_t)srow * 256;
            uint32_t sw = ((uint32_t)(skq * 2)) ^ s_swz;
            CP16(dbase + sw, src);
            CPCOMMIT();
        }

        // xg prefetch (overlaps staging latency)
        float xgv[4];
        if (updater) {
            const float* xp = g_xg + ((size_t)s * B_ + ub) * HID + j0 + uj;
#pragma unroll
            for (int g = 0; g < 4; g++) xgv[g] = xp[g * HS];
        }

        // parity accumulator chains over this warp's 2 k16 per chunk
        float cA[2][4] = {{0.f, 0.f, 0.f, 0.f}, {0.f, 0.f, 0.f, 0.f}};
        float cB[2][4] = {{0.f, 0.f, 0.f, 0.f}, {0.f, 0.f, 0.f, 0.f}};

#pragma unroll 1
        for (int ch = 0; ch < 8; ch++) {
            CPWAIT(2);
            __syncthreads();

            // stage chunk ch+3 into ring
            if (ch < 5) {
                const int nc = ch + 3;
                const __half* src = hsrc + srow * HS + nc * 128 + skq;
                uint32_t dbase = sb + SM_HST + (uint32_t)(nc & 3) * 16384u +
                                 (uint32_t)srow * 256;
                uint32_t sw = ((uint32_t)(skq * 2)) ^ s_swz;
                CP16(dbase + sw, src);
            }
            CPCOMMIT();

            const uint32_t abase = sb + SM_HST + (uint32_t)(ch & 3) * 16384u;
            const uint32_t kch2 = (uint32_t)(ch * 256) + kslice2;

            // software-pipelined frag loads over this warp's 2 k16
            uint32_t fA[2][4], fB[2][4];
            {
                uint32_t bo = b_row + ((kch2 + b_k2) ^ b_swz);
                LDSM4(fA[0][0], fA[0][1], fA[0][2], fA[0][3],
                      abase + a_row + ((kslice2 + a_k2) ^ a_swz));
                LDSM4(fB[0][0], fB[0][1], fB[0][2], fB[0][3], sb + SM_WH + bo);
            }
#pragma unroll
            for (int k16 = 0; k16 < 2; k16++) {
                const int cur = k16 & 1;
                const int nxt = cur ^ 1;
                if (k16 < 1) {
                    uint32_t ka = 32u;
                    uint32_t bo = b_row + ((kch2 + ka + b_k2) ^ b_swz);
                    LDSM4(fA[nxt][0], fA[nxt][1], fA[nxt][2], fA[nxt][3],
                          abase + a_row + ((kslice2 + ka + a_k2) ^ a_swz));
                    LDSM4(fB[nxt][0], fB[nxt][1], fB[nxt][2], fB[nxt][3],
                          sb + SM_WH + bo);
                }
                MMA16816(cA[cur], fA[cur][0], fA[cur][1], fA[cur][2], fA[cur][3],
                         fB[cur][0], fB[cur][1]);
                MMA16816(cB[cur], fA[cur][0], fA[cur][1], fA[cur][2], fA[cur][3],
                         fB[cur][2], fB[cur][3]);
            }
        }

        // merge parity chains + scatter to this k-slice's gates region
        {
            float* pb = gates + ks * (64 * 34);
            const int tr = lane >> 2;
            const int tc = (lane & 3) * 2;
            const int br = wm + tr;
            pb[(br + 0) * 34 + wn + tc + 0] = cA[0][0] + cA[1][0];
            pb[(br + 0) * 34 + wn + tc + 1] = cA[0][1] + cA[1][1];
            pb[(br + 8) * 34 + wn + tc + 0] = cA[0][2] + cA[1][2];
            pb[(br + 8) * 34 + wn + tc + 1] = cA[0][3] + cA[1][3];
            pb[(br + 0) * 34 + wn + 8 + tc + 0] = cB[0][0] + cB[1][0];
            pb[(br + 0) * 34 + wn + 8 + tc + 1] = cB[0][1] + cB[1][1];
            pb[(br + 8) * 34 + wn + 8 + tc + 0] = cB[0][2] + cB[1][2];
            pb[(br + 8) * 34 + wn + 8 + tc + 1] = cB[0][3] + cB[1][3];
        }
        __syncthreads();

        // distributed update: threads 0..511, each handles (batch ub, unit uj)
        float hn = 0.0f;
        if (updater) {
            const float* g0 = gates + 0 * (64 * 34) + ub * 34;
            const float* g1 = gates + 1 * (64 * 34) + ub * 34;
            const float* g2 = gates + 2 * (64 * 34) + ub * 34;
            const float* g3 = gates + 3 * (64 * 34) + ub * 34;
            float gi = (g0[0 + uj] + g1[0 + uj]) + (g2[0 + uj] + g3[0 + uj]) + xgv[0];
            float gf = (g0[8 + uj] + g1[8 + uj]) + (g2[8 + uj] + g3[8 + uj]) + xgv[1];
            float gg = (g0[16 + uj] + g1[16 + uj]) + (g2[16 + uj] + g3[16 + uj]) + xgv[2];
            float go = (g0[24 + uj] + g1[24 + uj]) + (g2[24 + uj] + g3[24 + uj]) + xgv[3];
            float iv = sigf(gi);
            float fv = sigf(gf);
            float gv = tanhfast(gg);
            float ov = sigf(go);
            float c = fv * creg + iv * gv;
            creg = c;
            hn = ov * tanhfast(c);

            __half hv = __float2half_rn(hn);
            unsigned short hbits = *(unsigned short*)&hv;
            asm volatile("st.release.gpu.global.b16 [%0], %1;"
                         :: "l"((unsigned short*)&g_hh[p ^ 1][ub * HS + j0 + uj]),
                            "h"(hbits) : "memory");
        }

        grid_barrier((unsigned)(s + 1) * (unsigned)gridDim.x);

        // fp32 out store AFTER the barrier (overlaps next step's staging)
        if (updater) {
            out[((size_t)ub * S_ + s) * HS + j0 + uj] = hn;
            if (do_tail && s == S_ - 1) {
                const size_t base = (size_t)B_ * S_ * HS;
                out[base + (size_t)ub * HS + j0 + uj] = hn;
                out[base + (size_t)B_ * HS + (size_t)ub * HS + j0 + uj] = creg;
            }
        }
    }
}

extern "C" void kernel_launch(void* const* d_in, const int* in_sizes, int n_in,
                              void* d_out, int out_size) {
    const float* x = (const float*)d_in[0];
    const float* wx = (const float*)d_in[1];
    const float* wh = (const float*)d_in[2];
    const float* bx = (const float*)d_in[3];
    const float* bh = (const float*)d_in[4];
    float* out = (float*)d_out;

    init_state<<<(B_ * HS / 2 + 255) / 256, 256>>>();
    convert_inputs<<<2048, 256>>>(x, wx);

    cudaFuncSetAttribute(xg_gemm_mma, cudaFuncAttributeMaxDynamicSharedMemorySize,
                         XG_SMEM);
    dim3 ga(S_ * B_ / 128, HID / 128);   // (256, 32)
    xg_gemm_mma<<<ga, 256, XG_SMEM>>>(bx, bh);

    cudaFuncSetAttribute(lstm_persist, cudaFuncAttributeMaxDynamicSharedMemorySize,
                         SMEM_TOTAL);
    int do_tail =
        ((long long)out_size >= (long long)B_ * S_ * HS + 2LL * B_ * HS) ? 1 : 0;
    lstm_persist<<<NCTA, RTHREADS, SMEM_TOTAL>>>(wh, out, do_tail);
}

// round 15
// speedup vs baseline: 1.0539x; 1.0539x over previous
#include <cuda_runtime.h>
#include <cuda_fp16.h>
#include <math.h>
#include <stdint.h>

#define B_ 64
#define S_ 512
#define DIN 1024
#define HID 4096
#define HS 1024
#define NCTA 128
#define RTHREADS 512

// ---------------------------------------------------------------------------
// helpers
// ---------------------------------------------------------------------------
__device__ __forceinline__ uint32_t smem_to_u32(const void* p) {
    uint32_t a;
    asm("{ .reg .u64 t; cvta.to.shared.u64 t, %1; cvt.u32.u64 %0, t; }"
        : "=r"(a) : "l"(p));
    return a;
}

#define LDSM4(r0, r1, r2, r3, addr)                                        \
    asm volatile("ldmatrix.sync.aligned.m8n8.x4.shared.b16 {%0,%1,%2,%3}, [%4];" \
                 : "=r"(r0), "=r"(r1), "=r"(r2), "=r"(r3) : "r"(addr))

#define MMA16816(c, a0, a1, a2, a3, b0, b1)                                \
    asm volatile("mma.sync.aligned.m16n8k16.row.col.f32.f16.f16.f32 "      \
                 "{%0,%1,%2,%3}, {%4,%5,%6,%7}, {%8,%9}, {%0,%1,%2,%3};"   \
                 : "+f"((c)[0]), "+f"((c)[1]), "+f"((c)[2]), "+f"((c)[3])  \
                 : "r"(a0), "r"(a1), "r"(a2), "r"(a3), "r"(b0), "r"(b1))

#define CP16(d, s) \
    asm volatile("cp.async.cg.shared.global [%0], [%1], 16;" :: "r"(d), "l"(s))
#define CPCOMMIT() asm volatile("cp.async.commit_group;" ::: "memory")
#define CPWAIT(n) asm volatile("cp.async.wait_group %0;" :: "n"(n) : "memory")

// ---------------------------------------------------------------------------
// Globals (static scratch)
// ---------------------------------------------------------------------------
__device__ float g_xg[(size_t)S_ * B_ * HID];     // [s][b][4096]
__device__ __half g_xh[(size_t)B_ * S_ * DIN];    // x as fp16
__device__ __half g_wxh[(size_t)HID * DIN];       // wx (single-term fp16)
__device__ __half g_hh[2][B_ * HS];               // double-buffered hidden (fp16)
__device__ unsigned g_bar;

__global__ void init_state() {
    int t = blockIdx.x * blockDim.x + threadIdx.x;
    if (t == 0) g_bar = 0u;
    if (t < B_ * HS / 2) ((uint32_t*)g_hh[0])[t] = 0u;
}

// ---------------------------------------------------------------------------
// Convert x -> fp16, wx -> fp16 (single term)
// ---------------------------------------------------------------------------
__global__ void convert_inputs(const float* __restrict__ x,
                               const float* __restrict__ wx) {
    int t = blockIdx.x * blockDim.x + threadIdx.x;
    int stride = gridDim.x * blockDim.x;
    for (int i = t; i < HID * DIN / 4; i += stride) {
        float4 w = ((const float4*)wx)[i];
        ((__half2*)g_wxh)[i * 2 + 0] =
            __half2(__float2half_rn(w.x), __float2half_rn(w.y));
        ((__half2*)g_wxh)[i * 2 + 1] =
            __half2(__float2half_rn(w.z), __float2half_rn(w.w));
    }
    for (int i = t; i < B_ * S_ * DIN / 4; i += stride) {
        float4 v = ((const float4*)x)[i];
        ((__half2*)g_xh)[i * 2 + 0] = __half2(__float2half_rn(v.x), __float2half_rn(v.y));
        ((__half2*)g_xh)[i * 2 + 1] = __half2(__float2half_rn(v.z), __float2half_rn(v.w));
    }
}

// ---------------------------------------------------------------------------
// xg GEMM via mma.sync (single-term fp16) — 2 CTAs/SM (R14, measured good)
// ---------------------------------------------------------------------------
#define XG_SA 0
#define XG_SB 32768
#define XG_SMEM 65536

__global__ void __launch_bounds__(256, 2)
xg_gemm_mma(const float* __restrict__ bx, const float* __restrict__ bh) {
    extern __shared__ char smem[];
    uint32_t sb = smem_to_u32(smem);
    const int tid = threadIdx.x;
    const int wid = tid >> 5;
    const int lane = tid & 31;
    const int m0 = blockIdx.x * 128;
    const int n0 = blockIdx.y * 128;
    const int wm = (wid >> 2) * 64;
    const int wn = (wid & 3) * 32;

    const int sr = tid >> 1;
    const int sq0 = (tid & 1) * 4;
    const uint32_t s_sw = (uint32_t)((sr & 7) << 4);
    const int am = m0 + sr;
    const __half* asrc = g_xh + ((size_t)((am & 63) * S_ + (am >> 6))) * DIN;
    const __half* bsrc = g_wxh + (size_t)(n0 + sr) * DIN;

    const uint32_t a_k2 = (uint32_t)((lane >> 4) << 4);
    uint32_t a_base[4], a_swz[4];
#pragma unroll
    for (int mi = 0; mi < 4; mi++) {
        int ar = wm + mi * 16 + (lane & 15);
        a_base[mi] = (uint32_t)ar * 128;
        a_swz[mi] = (uint32_t)((ar & 7) << 4);
    }
    const uint32_t b_k2 = (uint32_t)(((lane >> 3) & 1) << 4);
    uint32_t b_base[2], b_swz[2];
#pragma unroll
    for (int ni = 0; ni < 2; ni++) {
        int bc = wn + ni * 16 + (lane & 7) + ((lane >> 4) << 3);
        b_base[ni] = (uint32_t)bc * 128;
        b_swz[ni] = (uint32_t)((bc & 7) << 4);
    }

    float acc[4][4][4];
#pragma unroll
    for (int i = 0; i < 4; i++)
#pragma unroll
        for (int j = 0; j < 4; j++)
#pragma unroll
            for (int q = 0; q < 4; q++) acc[i][j][q] = 0.0f;

    {
        uint32_t da = sb + XG_SA + (uint32_t)sr * 128;
        uint32_t db = sb + XG_SB + (uint32_t)sr * 128;
#pragma unroll
        for (int j = 0; j < 4; j++) {
            int q = sq0 + j;
            uint32_t sw = ((uint32_t)(q * 16)) ^ s_sw;
            CP16(da + sw, asrc + q * 8);
            CP16(db + sw, bsrc + q * 8);
        }
        CPCOMMIT();
    }

#pragma unroll 1
    for (int ch = 0; ch < 16; ch++) {
        const uint32_t buf = (uint32_t)(ch & 1);
        if (ch < 15) {
            const int kb = (ch + 1) * 64;
            uint32_t da = sb + XG_SA + (buf ^ 1u) * 16384u + (uint32_t)sr * 128;
            uint32_t db = sb + XG_SB + (buf ^ 1u) * 16384u + (uint32_t)sr * 128;
#pragma unroll
            for (int j = 0; j < 4; j++) {
                int q = sq0 + j;
                uint32_t sw = ((uint32_t)(q * 16)) ^ s_sw;
                CP16(da + sw, asrc + kb + q * 8);
                CP16(db + sw, bsrc + kb + q * 8);
            }
            CPCOMMIT();
            CPWAIT(1);
        } else {
            CPWAIT(0);
        }
        __syncthreads();

        const uint32_t abase = sb + XG_SA + buf * 16384u;
        const uint32_t bbase = sb + XG_SB + buf * 16384u;
#pragma unroll
        for (int k16 = 0; k16 < 4; k16++) {
            const uint32_t ka = (uint32_t)(k16 * 32);
            uint32_t a[4][4];
#pragma unroll
            for (int mi = 0; mi < 4; mi++)
                LDSM4(a[mi][0], a[mi][1], a[mi][2], a[mi][3],
                      abase + a_base[mi] + ((ka + a_k2) ^ a_swz[mi]));
            uint32_t bf[2][4];
#pragma unroll
            for (int ni = 0; ni < 2; ni++) {
                uint32_t bo = b_base[ni] + ((ka + b_k2) ^ b_swz[ni]);
                LDSM4(bf[ni][0], bf[ni][1], bf[ni][2], bf[ni][3], bbase + bo);
            }
#pragma unroll
            for (int mi = 0; mi < 4; mi++)
#pragma unroll
                for (int ni = 0; ni < 2; ni++) {
                    MMA16816(acc[mi][ni * 2 + 0], a[mi][0], a[mi][1], a[mi][2],
                             a[mi][3], bf[ni][0], bf[ni][1]);
                    MMA16816(acc[mi][ni * 2 + 1], a[mi][0], a[mi][1], a[mi][2],
                             a[mi][3], bf[ni][2], bf[ni][3]);
                }
        }
        __syncthreads();
    }

    const int tr = lane >> 2;
    const int tc = (lane & 3) * 2;
#pragma unroll
    for (int ni = 0; ni < 4; ni++) {
        int n = n0 + wn + ni * 8 + tc;
        float b0 = bx[n] + bh[n];
        float b1 = bx[n + 1] + bh[n + 1];
#pragma unroll
        for (int mi = 0; mi < 4; mi++) {
            int mrow = m0 + wm + mi * 16 + tr;
            float* d0 = g_xg + (size_t)mrow * HID + n;
            float* d1 = g_xg + (size_t)(mrow + 8) * HID + n;
            *(float2*)d0 = make_float2(acc[mi][ni][0] + b0, acc[mi][ni][1] + b1);
            *(float2*)d1 = make_float2(acc[mi][ni][2] + b0, acc[mi][ni][3] + b1);
        }
    }
}

// ---------------------------------------------------------------------------
// Persistent recurrence: R13 version verbatim (512 threads, k-split-2)
// ---------------------------------------------------------------------------
__device__ __forceinline__ float sigf(float x) { return 1.0f / (1.0f + __expf(-x)); }
__device__ __forceinline__ float tanhfast(float x) {
    float ax = fabsf(x);
    float e = __expf(-2.0f * ax);
    float r = (1.0f - e) / (1.0f + e);
    return copysignf(r, x);
}

__device__ __forceinline__ void grid_barrier(unsigned target) {
    __syncthreads();
    if (threadIdx.x == 0) {
        asm volatile("red.release.gpu.global.add.u32 [%0], %1;"
                     :: "l"(&g_bar), "r"(1u) : "memory");
        unsigned v;
        do {
            asm volatile("ld.acquire.gpu.global.u32 %0, [%1];"
                         : "=r"(v) : "l"(&g_bar));
        } while ((int)(v - target) < 0);
    }
    __syncthreads();
}

// smem layout (bytes)
#define SM_WH 0              /* 32 cols x 2048 B = 65536 */
#define SM_HST 65536         /* 4 ring bufs x 16KB = 65536 */
#define SM_GATES 131072      /* 2 k-slices x 64 x 34 f32 = 17408 */
#define SMEM_TOTAL (SM_GATES + 2 * 64 * 34 * 4)

__global__ void __launch_bounds__(RTHREADS, 1)
lstm_persist(const float* __restrict__ wh, float* __restrict__ out, int do_tail) {
    extern __shared__ char smem[];
    uint32_t sb = smem_to_u32(smem);
    float* gates = (float*)(smem + SM_GATES);

    const int tid = threadIdx.x;
    const int wid = tid >> 5;
    const int lane = tid & 31;
    const int j0 = blockIdx.x * 8;

    // --- one-time: this CTA's 32 wh rows as fp16 into smem [col][k] ---
    {
        const int c = tid >> 4;                      // col 0..31
        const int kb = (tid & 15) * 64;              // k base (64 k per thread)
        const int n = (c >> 3) * HS + j0 + (c & 7);
        const float* wr = wh + (size_t)n * HS;
        const uint32_t swz = (uint32_t)((c & 7) << 4);
#pragma unroll 4
        for (int i = 0; i < 16; i++) {
            int k = kb + i * 4;
            float4 w4 = *(const float4*)(wr + k);
            __half h0 = __float2half_rn(w4.x);
            __half h1 = __float2half_rn(w4.y);
            __half h2 = __float2half_rn(w4.z);
            __half h3 = __float2half_rn(w4.w);
            uint32_t off = (uint32_t)(c * 2048) + (((uint32_t)(k * 2)) ^ swz);
            *(__half2*)(smem + SM_WH + off) = __half2(h0, h1);
            *(__half2*)(smem + SM_WH + off + 4) = __half2(h2, h3);
        }
    }
    __syncthreads();

    // warp decomposition: ks = k-slice (half-chunk), wm/wn as in R7
    const int ks = wid >> 3;                 // 0 or 1
    const int wsub = wid & 7;
    const int wm = (wsub >> 1) << 4;
    const int wn = (wsub & 1) << 4;

    // A ldmatrix (16x16 tile, 256B rows in 16KB ring buf, swizzled)
    const int ar = wm + (lane & 15);
    const uint32_t a_row = (uint32_t)ar * 256;
    const uint32_t a_k2 = (uint32_t)((lane >> 4) << 4);
    const uint32_t a_swz = (uint32_t)((ar & 7) << 4);

    // B ldmatrix (cols as rows, 2048B col stride, swizzled)
    const int bc = wn + (lane & 7) + ((lane >> 4) << 3);
    const uint32_t b_row = (uint32_t)bc * 2048;
    const uint32_t b_k2 = (uint32_t)(((lane >> 3) & 1) << 4);
    const uint32_t b_swz = (uint32_t)((bc & 7) << 4);

    // this warp's k offset within a chunk (bytes): ks half = 4 k16 = 128 B
    const uint32_t kslice2 = (uint32_t)(ks * 128);

    // cp.async staging: 512 threads, row = tid>>3, 16 k elems (32B) each
    const int srow = tid >> 3;
    const int skq = (tid & 7) * 16;
    const uint32_t s_swz = (uint32_t)((srow & 7) << 4);

    // distributed update: 1 (batch, unit) pair per thread
    const int ub = tid >> 3;                 // batch 0..63
    const int uj = tid & 7;                  // unit 0..7

    float creg = 0.0f;

    for (int s = 0; s < S_; s++) {
        const int p = s & 1;
        const __half* hsrc = g_hh[p];

        // stage chunks 0,1,2 first (start L2 fetch ASAP)
#pragma unroll
        for (int c0 = 0; c0 < 3; c0++) {
            const __half* src = hsrc + srow * HS + c0 * 128 + skq;
            uint32_t dbase = sb + SM_HST + (uint32_t)c0 * 16384u +
                             (uint32_t)srow * 256;
#pragma unroll
            for (int j = 0; j < 2; j++) {
                uint32_t sw = ((uint32_t)((skq + j * 8) * 2)) ^ s_swz;
                CP16(dbase + sw, src + j * 8);
            }
            CPCOMMIT();
        }

        // xg prefetch (overlaps staging latency)
        float xgv[4];
        {
            const float* xp = g_xg + ((size_t)s * B_ + ub) * HID + j0 + uj;
#pragma unroll
            for (int g = 0; g < 4; g++) xgv[g] = xp[g * HS];
        }

        // 4 independent accumulator chains (k16-parity within this warp's slice)
        float cA[2][4] = {{0.f, 0.f, 0.f, 0.f}, {0.f, 0.f, 0.f, 0.f}};
        float cB[2][4] = {{0.f, 0.f, 0.f, 0.f}, {0.f, 0.f, 0.f, 0.f}};

#pragma unroll 1
        for (int ch = 0; ch < 8; ch++) {
            CPWAIT(2);
            __syncthreads();

            // stage chunk ch+3 into ring
            if (ch < 5) {
                const int nc = ch + 3;
                const __half* src = hsrc + srow * HS + nc * 128 + skq;
                uint32_t dbase = sb + SM_HST + (uint32_t)(nc & 3) * 16384u +
                                 (uint32_t)srow * 256;
#pragma unroll
                for (int j = 0; j < 2; j++) {
                    uint32_t sw = ((uint32_t)((skq + j * 8) * 2)) ^ s_swz;
                    CP16(dbase + sw, src + j * 8);
                }
            }
            CPCOMMIT();

            const uint32_t abase = sb + SM_HST + (uint32_t)(ch & 3) * 16384u;
            const uint32_t kch2 = (uint32_t)(ch * 256) + kslice2;

            // software-pipelined frag loads over this warp's 4 k16
            uint32_t fA[2][4], fB[2][4];
            {
                uint32_t bo = b_row + ((kch2 + b_k2) ^ b_swz);
                LDSM4(fA[0][0], fA[0][1], fA[0][2], fA[0][3],
                      abase + a_row + ((kslice2 + a_k2) ^ a_swz));
                LDSM4(fB[0][0], fB[0][1], fB[0][2], fB[0][3], sb + SM_WH + bo);
            }
#pragma unroll
            for (int k16 = 0; k16 < 4; k16++) {
                const int cur = k16 & 1;
                const int nxt = cur ^ 1;
                if (k16 < 3) {
                    uint32_t ka = (uint32_t)((k16 + 1) * 32);
                    uint32_t bo = b_row + ((kch2 + ka + b_k2) ^ b_swz);
                    LDSM4(fA[nxt][0], fA[nxt][1], fA[nxt][2], fA[nxt][3],
                          abase + a_row + ((kslice2 + ka + a_k2) ^ a_swz));
                    LDSM4(fB[nxt][0], fB[nxt][1], fB[nxt][2], fB[nxt][3],
                          sb + SM_WH + bo);
                }
                MMA16816(cA[cur], fA[cur][0], fA[cur][1], fA[cur][2], fA[cur][3],
                         fB[cur][0], fB[cur][1]);
                MMA16816(cB[cur], fA[cur][0], fA[cur][1], fA[cur][2], fA[cur][3],
                         fB[cur][2], fB[cur][3]);
            }
        }

        // merge parity chains + scatter to this k-slice's gates region
        {
            float* pb = gates + ks * (64 * 34);
            const int tr = lane >> 2;
            const int tc = (lane & 3) * 2;
            const int br = wm + tr;
            pb[(br + 0) * 34 + wn + tc + 0] = cA[0][0] + cA[1][0];
            pb[(br + 0) * 34 + wn + tc + 1] = cA[0][1] + cA[1][1];
            pb[(br + 8) * 34 + wn + tc + 0] = cA[0][2] + cA[1][2];
            pb[(br + 8) * 34 + wn + tc + 1] = cA[0][3] + cA[1][3];
            pb[(br + 0) * 34 + wn + 8 + tc + 0] = cB[0][0] + cB[1][0];
            pb[(br + 0) * 34 + wn + 8 + tc + 1] = cB[0][1] + cB[1][1];
            pb[(br + 8) * 34 + wn + 8 + tc + 0] = cB[0][2] + cB[1][2];
            pb[(br + 8) * 34 + wn + 8 + tc + 1] = cB[0][3] + cB[1][3];
        }
        __syncthreads();

        // distributed update: each thread handles (batch ub, unit uj)
        float hn;
        {
            const float* g0 = gates + ub * 34;
            const float* g1 = gates + 64 * 34 + ub * 34;
            float gi = g0[0 + uj] + g1[0 + uj] + xgv[0];
            float gf = g0[8 + uj] + g1[8 + uj] + xgv[1];
            float gg = g0[16 + uj] + g1[16 + uj] + xgv[2];
            float go = g0[24 + uj] + g1[24 + uj] + xgv[3];
            float iv = sigf(gi);
            float fv = sigf(gf);
            float gv = tanhfast(gg);
            float ov = sigf(go);
            float c = fv * creg + iv * gv;
            creg = c;
            hn = ov * tanhfast(c);

            __half hv = __float2half_rn(hn);
            unsigned short hbits = *(unsigned short*)&hv;
            asm volatile("st.release.gpu.global.b16 [%0], %1;"
                         :: "l"((unsigned short*)&g_hh[p ^ 1][ub * HS + j0 + uj]),
                            "h"(hbits) : "memory");
        }

        grid_barrier((unsigned)(s + 1) * (unsigned)gridDim.x);

        // fp32 out store AFTER the barrier (overlaps next step's staging)
        out[((size_t)ub * S_ + s) * HS + j0 + uj] = hn;

        if (do_tail && s == S_ - 1) {
            const size_t base = (size_t)B_ * S_ * HS;
            out[base + (size_t)ub * HS + j0 + uj] = hn;
            out[base + (size_t)B_ * HS + (size_t)ub * HS + j0 + uj] = creg;
        }
    }
}

extern "C" void kernel_launch(void* const* d_in, const int* in_sizes, int n_in,
                              void* d_out, int out_size) {
    const float* x = (const float*)d_in[0];
    const float* wx = (const float*)d_in[1];
    const float* wh = (const float*)d_in[2];
    const float* bx = (const float*)d_in[3];
    const float* bh = (const float*)d_in[4];
    float* out = (float*)d_out;

    init_state<<<(B_ * HS / 2 + 255) / 256, 256>>>();
    convert_inputs<<<2048, 256>>>(x, wx);

    cudaFuncSetAttribute(xg_gemm_mma, cudaFuncAttributeMaxDynamicSharedMemorySize,
                         XG_SMEM);
    dim3 ga(S_ * B_ / 128, HID / 128);   // (256, 32)
    xg_gemm_mma<<<ga, 256, XG_SMEM>>>(bx, bh);

    cudaFuncSetAttribute(lstm_persist, cudaFuncAttributeMaxDynamicSharedMemorySize,
                         SMEM_TOTAL);
    int do_tail =
        ((long long)out_size >= (long long)B_ * S_ * HS + 2LL * B_ * HS) ? 1 : 0;
    lstm_persist<<<NCTA, RTHREADS, SMEM_TOTAL>>>(wh, out, do_tail);
}